// round 14
// baseline (speedup 1.0000x reference)
#include <cuda_runtime.h>
#include <cuda_bf16.h>

// PointLayerNorm, R14: R12 structure (measured best, 155.4us) with the norm
// launched as a single co-resident wave (591 blocks: 148 SMs x 4 CTAs minus
// one; 591*256 divisible by 24) to remove the wave-2 transition and tail.
// R13's finalize-fold reverted (added a reduce tail; measured worse).

#define Bc 4
#define Nc 200000
#define Cc 96
#define C4 (Cc / 4)            // 24 float4 per point
#define Sc 32
#define KEYS (Bc * Sc)
#define EPSF 1e-5f
#define RGRID 148              // one 1024-thread CTA per SM
#define RTPB 1024
#define NGRID 591              // single wave; divisible by 3

__device__ float g_sum[KEYS];    // static zero-init; re-zeroed by finalize
__device__ float g_sumsq[KEYS];
__device__ float4 g_sc[KEYS * C4];   // per (key, c4) scale
__device__ float4 g_sh[KEYS * C4];   // per (key, c4) shift

__device__ __forceinline__ void acc4(const float4 v, float& s, float& s2) {
    s += (v.x + v.y) + (v.z + v.w);
    s2 = fmaf(v.x, v.x, s2); s2 = fmaf(v.y, v.y, s2);
    s2 = fmaf(v.z, v.z, s2); s2 = fmaf(v.w, v.w, s2);
}

// Reduce: one warp owns a contiguous range of global points [g0, g1).
// Segment runs derived from the 33-entry offs array (batch_indices is
// non-decreasing) -> no idx loads, no shuffles/ballots in the hot loop.
__global__ __launch_bounds__(RTPB, 1) void pln_reduce_kernel(
    const float4* __restrict__ x4, const int* __restrict__ offs)
{
    const int P = Bc * Nc;
    int wid    = (blockIdx.x * blockDim.x + threadIdx.x) >> 5;
    int lane   = threadIdx.x & 31;
    int totalW = (RGRID * RTPB) >> 5;                        // 4736 warps
    int chunk  = (((P + totalW - 1) / totalW) + 15) & ~15;   // 176
    int g0 = wid * chunk;
    int g1 = min(g0 + chunk, P);
    if (g0 >= g1) return;

    int g = g0;
    while (g < g1) {
        int b = g / Nc;
        int n = g - b * Nc;
        int nlimit = min(Nc, n + (g1 - g));     // batch-local end of our range

        // binary search: largest seg with offs[seg] <= n  (offs[0]=0)
        int seg = 0;
        #pragma unroll
        for (int step = 16; step; step >>= 1) {
            int cand = seg + step;
            if (cand <= Sc - 1 && __ldg(&offs[cand]) <= n) seg = cand;
        }

        while (n < nlimit) {
            int rend = min(nlimit, __ldg(&offs[seg + 1]));
            int key  = b * Sc + seg;

            float sA = 0.f, sB = 0.f, s2A = 0.f, s2B = 0.f;
            const float4* base = x4 + ((size_t)b * Nc + n) * C4;

            // 16-point groups: 384 consecutive float4s, 12 LDG.128 per lane.
            for (; n + 16 <= rend; n += 16, base += 384) {
                float4 v0  = __ldg(base + lane);
                float4 v1  = __ldg(base + lane + 32);
                float4 v2  = __ldg(base + lane + 64);
                float4 v3  = __ldg(base + lane + 96);
                float4 v4  = __ldg(base + lane + 128);
                float4 v5  = __ldg(base + lane + 160);
                float4 v6  = __ldg(base + lane + 192);
                float4 v7  = __ldg(base + lane + 224);
                float4 v8  = __ldg(base + lane + 256);
                float4 v9  = __ldg(base + lane + 288);
                float4 v10 = __ldg(base + lane + 320);
                float4 v11 = __ldg(base + lane + 352);
                acc4(v0,  sA, s2A); acc4(v1,  sB, s2B);
                acc4(v2,  sA, s2A); acc4(v3,  sB, s2B);
                acc4(v4,  sA, s2A); acc4(v5,  sB, s2B);
                acc4(v6,  sA, s2A); acc4(v7,  sB, s2B);
                acc4(v8,  sA, s2A); acc4(v9,  sB, s2B);
                acc4(v10, sA, s2A); acc4(v11, sB, s2B);
            }
            // 8-point group (at most one)
            for (; n + 8 <= rend; n += 8, base += 192) {
                float4 v0 = __ldg(base + lane);
                float4 v1 = __ldg(base + lane + 32);
                float4 v2 = __ldg(base + lane + 64);
                float4 v3 = __ldg(base + lane + 96);
                float4 v4 = __ldg(base + lane + 128);
                float4 v5 = __ldg(base + lane + 160);
                acc4(v0, sA, s2A); acc4(v1, sB, s2B);
                acc4(v2, sA, s2A); acc4(v3, sB, s2B);
                acc4(v4, sA, s2A); acc4(v5, sB, s2B);
            }
            // remainder: single points, 24 active lanes
            for (; n < rend; ++n, base += 24) {
                if (lane < C4) {
                    float4 v = __ldg(base + lane);
                    acc4(v, sA, s2A);
                }
            }

            // flush this run
            float s = sA + sB, s2 = s2A + s2B;
            #pragma unroll
            for (int o = 16; o; o >>= 1) {
                s  += __shfl_xor_sync(0xffffffffu, s,  o);
                s2 += __shfl_xor_sync(0xffffffffu, s2, o);
            }
            if (lane == 0) {
                atomicAdd(&g_sum[key],   s);
                atomicAdd(&g_sumsq[key], s2);
            }
            if (n < nlimit) ++seg;   // next segment in this batch
        }
        g = b * Nc + nlimit;         // next batch-slice re-searches seg
    }
}

// Per-(key, c4) scale/shift tables, then zero the stats for the next replay.
__global__ void pln_finalize_kernel(const int* __restrict__ offs,
                                    const float4* __restrict__ w4,
                                    const float4* __restrict__ b4)
{
    int i = blockIdx.x * blockDim.x + threadIdx.x;
    if (i < KEYS * C4) {
        int k  = i / C4;
        int c4 = i - k * C4;
        int seg = k & (Sc - 1);
        float cnt = (float)(offs[seg + 1] - offs[seg]) * (float)Cc;
        float m   = g_sum[k] / cnt;
        float var = g_sumsq[k] / cnt - m * m;
        float iv  = rsqrtf(var + EPSF);
        float4 wv = __ldg(w4 + c4);
        float4 bv = __ldg(b4 + c4);
        float4 sc, sh;
        sc.x = iv * wv.x; sh.x = fmaf(-m, sc.x, bv.x);
        sc.y = iv * wv.y; sh.y = fmaf(-m, sc.y, bv.y);
        sc.z = iv * wv.z; sh.z = fmaf(-m, sc.z, bv.z);
        sc.w = iv * wv.w; sh.w = fmaf(-m, sc.w, bv.w);
        g_sc[i] = sc;
        g_sh[i] = sh;
        if (c4 == 0) {                // one thread per key zeroes its stats
            g_sum[k]   = 0.f;
            g_sumsq[k] = 0.f;
        }
    }
}

// Norm: R10/R12 body, single-wave grid-stride (591 co-resident blocks).
__global__ __launch_bounds__(256) void pln_norm_kernel(
    const float4* __restrict__ x4, const int* __restrict__ idx,
    float4* __restrict__ out4)
{
    const int P = Bc * Nc;
    const int E = P * C4;                      // 19,200,000 float4s
    int T   = NGRID * 256;                     // 151,296, multiple of 24
    int tid = blockIdx.x * blockDim.x + threadIdx.x;
    int dp  = T / C4;                          // 6304

    int p  = tid / C4;
    int c4 = tid - p * C4;
    int b  = p / Nc;
    int n  = p - b * Nc;

    for (int e = tid; e < E; e += T) {
        int key = (b * Sc + __ldg(&idx[n])) & (KEYS - 1);
        int t   = key * C4 + c4;
        float4 sc = g_sc[t];
        float4 sh = g_sh[t];
        float4 xv = __ldcs(x4 + e);
        float4 o;
        o.x = fmaf(xv.x, sc.x, sh.x);
        o.y = fmaf(xv.y, sc.y, sh.y);
        o.z = fmaf(xv.z, sc.z, sh.z);
        o.w = fmaf(xv.w, sc.w, sh.w);
        __stcs(out4 + e, o);
        n += dp;
        if (n >= Nc) { n -= Nc; ++b; }
    }
}

extern "C" void kernel_launch(void* const* d_in, const int* in_sizes, int n_in,
                              void* d_out, int out_size) {
    const float4* x4   = (const float4*)d_in[0];
    const int*    offs = (const int*)d_in[1];
    const int*    idx  = (const int*)d_in[2];
    const float4* w4   = (const float4*)d_in[3];
    const float4* b4   = (const float4*)d_in[4];
    float4* out4 = (float4*)d_out;

    pln_reduce_kernel<<<RGRID, RTPB>>>(x4, offs);
    pln_finalize_kernel<<<12, 256>>>(offs, w4, b4);
    pln_norm_kernel<<<NGRID, 256>>>(x4, idx, out4);
}

// round 15
// speedup vs baseline: 1.0956x; 1.0956x over previous
#include <cuda_runtime.h>
#include <cuda_bf16.h>

// PointLayerNorm, R15 == R12 (measured best: 155.4us). Final form.
// - reduce: one 1024-thread CTA per SM (148 CTAs), warp-contiguous point
//   ranges, segment runs derived from the 33-entry offs array (batch_indices
//   is non-decreasing) -> pure 12x LDG.128 + FMA stream, 76% DRAM (~6.05TB/s).
// - finalize: builds per-(key,channel) scale/shift tables, re-zeroes stats
//   (replay-deterministic; first call relies on static zero-init).
// - norm: division-free grid-stride (c4 loop-invariant per thread), float4
//   streaming loads/stores, ~6.3TB/s mixed R/W (practical DRAM ceiling).
// Traffic floor 921MB; R5/R7 established L2-reuse chunking loses more to
// launch/barrier granularity than it saves; R11/R14 established unroll x2 and
// single-wave norm both regress. This is the structural optimum found.

#define Bc 4
#define Nc 200000
#define Cc 96
#define C4 (Cc / 4)            // 24 float4 per point
#define Sc 32
#define KEYS (Bc * Sc)
#define EPSF 1e-5f
#define RGRID 148              // one 1024-thread CTA per SM
#define RTPB 1024

__device__ float g_sum[KEYS];    // static zero-init; re-zeroed by finalize
__device__ float g_sumsq[KEYS];
__device__ float4 g_sc[KEYS * C4];   // per (key, c4) scale
__device__ float4 g_sh[KEYS * C4];   // per (key, c4) shift

__device__ __forceinline__ void acc4(const float4 v, float& s, float& s2) {
    s += (v.x + v.y) + (v.z + v.w);
    s2 = fmaf(v.x, v.x, s2); s2 = fmaf(v.y, v.y, s2);
    s2 = fmaf(v.z, v.z, s2); s2 = fmaf(v.w, v.w, s2);
}

// Reduce: one warp owns a contiguous range of global points [g0, g1).
__global__ __launch_bounds__(RTPB, 1) void pln_reduce_kernel(
    const float4* __restrict__ x4, const int* __restrict__ offs)
{
    const int P = Bc * Nc;
    int wid    = (blockIdx.x * blockDim.x + threadIdx.x) >> 5;
    int lane   = threadIdx.x & 31;
    int totalW = (RGRID * RTPB) >> 5;                        // 4736 warps
    int chunk  = (((P + totalW - 1) / totalW) + 15) & ~15;   // 176
    int g0 = wid * chunk;
    int g1 = min(g0 + chunk, P);
    if (g0 >= g1) return;

    int g = g0;
    while (g < g1) {
        int b = g / Nc;
        int n = g - b * Nc;
        int nlimit = min(Nc, n + (g1 - g));     // batch-local end of our range

        // binary search: largest seg with offs[seg] <= n  (offs[0]=0)
        int seg = 0;
        #pragma unroll
        for (int step = 16; step; step >>= 1) {
            int cand = seg + step;
            if (cand <= Sc - 1 && __ldg(&offs[cand]) <= n) seg = cand;
        }

        while (n < nlimit) {
            int rend = min(nlimit, __ldg(&offs[seg + 1]));
            int key  = b * Sc + seg;

            float sA = 0.f, sB = 0.f, s2A = 0.f, s2B = 0.f;
            const float4* base = x4 + ((size_t)b * Nc + n) * C4;

            // 16-point groups: 384 consecutive float4s, 12 LDG.128 per lane.
            for (; n + 16 <= rend; n += 16, base += 384) {
                float4 v0  = __ldg(base + lane);
                float4 v1  = __ldg(base + lane + 32);
                float4 v2  = __ldg(base + lane + 64);
                float4 v3  = __ldg(base + lane + 96);
                float4 v4  = __ldg(base + lane + 128);
                float4 v5  = __ldg(base + lane + 160);
                float4 v6  = __ldg(base + lane + 192);
                float4 v7  = __ldg(base + lane + 224);
                float4 v8  = __ldg(base + lane + 256);
                float4 v9  = __ldg(base + lane + 288);
                float4 v10 = __ldg(base + lane + 320);
                float4 v11 = __ldg(base + lane + 352);
                acc4(v0,  sA, s2A); acc4(v1,  sB, s2B);
                acc4(v2,  sA, s2A); acc4(v3,  sB, s2B);
                acc4(v4,  sA, s2A); acc4(v5,  sB, s2B);
                acc4(v6,  sA, s2A); acc4(v7,  sB, s2B);
                acc4(v8,  sA, s2A); acc4(v9,  sB, s2B);
                acc4(v10, sA, s2A); acc4(v11, sB, s2B);
            }
            // 8-point group (at most one)
            for (; n + 8 <= rend; n += 8, base += 192) {
                float4 v0 = __ldg(base + lane);
                float4 v1 = __ldg(base + lane + 32);
                float4 v2 = __ldg(base + lane + 64);
                float4 v3 = __ldg(base + lane + 96);
                float4 v4 = __ldg(base + lane + 128);
                float4 v5 = __ldg(base + lane + 160);
                acc4(v0, sA, s2A); acc4(v1, sB, s2B);
                acc4(v2, sA, s2A); acc4(v3, sB, s2B);
                acc4(v4, sA, s2A); acc4(v5, sB, s2B);
            }
            // remainder: single points, 24 active lanes
            for (; n < rend; ++n, base += 24) {
                if (lane < C4) {
                    float4 v = __ldg(base + lane);
                    acc4(v, sA, s2A);
                }
            }

            // flush this run
            float s = sA + sB, s2 = s2A + s2B;
            #pragma unroll
            for (int o = 16; o; o >>= 1) {
                s  += __shfl_xor_sync(0xffffffffu, s,  o);
                s2 += __shfl_xor_sync(0xffffffffu, s2, o);
            }
            if (lane == 0) {
                atomicAdd(&g_sum[key],   s);
                atomicAdd(&g_sumsq[key], s2);
            }
            if (n < nlimit) ++seg;   // next segment in this batch
        }
        g = b * Nc + nlimit;         // next batch-slice re-searches seg
    }
}

// Per-(key, c4) scale/shift tables, then zero the stats for the next replay.
__global__ void pln_finalize_kernel(const int* __restrict__ offs,
                                    const float4* __restrict__ w4,
                                    const float4* __restrict__ b4)
{
    int i = blockIdx.x * blockDim.x + threadIdx.x;
    if (i < KEYS * C4) {
        int k  = i / C4;
        int c4 = i - k * C4;
        int seg = k & (Sc - 1);
        float cnt = (float)(offs[seg + 1] - offs[seg]) * (float)Cc;
        float m   = g_sum[k] / cnt;
        float var = g_sumsq[k] / cnt - m * m;
        float iv  = rsqrtf(var + EPSF);
        float4 wv = __ldg(w4 + c4);
        float4 bv = __ldg(b4 + c4);
        float4 sc, sh;
        sc.x = iv * wv.x; sh.x = fmaf(-m, sc.x, bv.x);
        sc.y = iv * wv.y; sh.y = fmaf(-m, sc.y, bv.y);
        sc.z = iv * wv.z; sh.z = fmaf(-m, sc.z, bv.z);
        sc.w = iv * wv.w; sh.w = fmaf(-m, sc.w, bv.w);
        g_sc[i] = sc;
        g_sh[i] = sh;
        if (c4 == 0) {                // one thread per key zeroes its stats
            g_sum[k]   = 0.f;
            g_sumsq[k] = 0.f;
        }
    }
}

// Norm: division-free grid-stride; 1185 blocks (2 waves) measured best.
__global__ __launch_bounds__(256) void pln_norm_kernel(
    const float4* __restrict__ x4, const int* __restrict__ idx,
    float4* __restrict__ out4)
{
    const int P = Bc * Nc;
    const int E = P * C4;                      // 19,200,000 float4s
    int T   = gridDim.x * blockDim.x;          // multiple of 24 by launch config
    int tid = blockIdx.x * blockDim.x + threadIdx.x;
    int dp  = T / C4;

    int p  = tid / C4;
    int c4 = tid - p * C4;
    int b  = p / Nc;
    int n  = p - b * Nc;

    for (int e = tid; e < E; e += T) {
        int key = (b * Sc + __ldg(&idx[n])) & (KEYS - 1);
        int t   = key * C4 + c4;
        float4 sc = g_sc[t];
        float4 sh = g_sh[t];
        float4 xv = __ldcs(x4 + e);
        float4 o;
        o.x = fmaf(xv.x, sc.x, sh.x);
        o.y = fmaf(xv.y, sc.y, sh.y);
        o.z = fmaf(xv.z, sc.z, sh.z);
        o.w = fmaf(xv.w, sc.w, sh.w);
        __stcs(out4 + e, o);
        n += dp;
        if (n >= Nc) { n -= Nc; ++b; }
    }
}

extern "C" void kernel_launch(void* const* d_in, const int* in_sizes, int n_in,
                              void* d_out, int out_size) {
    const float4* x4   = (const float4*)d_in[0];
    const int*    offs = (const int*)d_in[1];
    const int*    idx  = (const int*)d_in[2];
    const float4* w4   = (const float4*)d_in[3];
    const float4* b4   = (const float4*)d_in[4];
    float4* out4 = (float4*)d_out;

    pln_reduce_kernel<<<RGRID, RTPB>>>(x4, offs);
    pln_finalize_kernel<<<12, 256>>>(offs, w4, b4);
    // grid*256 divisible by 24 -> grid divisible by 3.
    pln_norm_kernel<<<1185, 256>>>(x4, idx, out4);
}

// round 16
// speedup vs baseline: 1.1221x; 1.0242x over previous
#include <cuda_runtime.h>
#include <cuda_bf16.h>

// PointLayerNorm, R16: two kernels total.
// - reduce: unchanged from R12/R15 (52us, DRAM ceiling); triggers PDL at end.
// - norm: finalize folded into a per-block prologue (128 (mean,inv) pairs in
//   smem); sc/sh derived in-loop (FMA pipe has 10x headroom). Stats zeroing
//   via last-block-done counter (replay-deterministic). Launched with
//   programmatic stream serialization so its ramp overlaps the reduce tail.

#define Bc 4
#define Nc 200000
#define Cc 96
#define C4 (Cc / 4)            // 24 float4 per point
#define Sc 32
#define KEYS (Bc * Sc)
#define EPSF 1e-5f
#define RGRID 148              // one 1024-thread CTA per SM
#define RTPB 1024
#define NGRID 1185             // norm grid (divisible by 3 -> T % 24 == 0)
#define NTPB 256

__device__ float g_sum[KEYS];    // static zero-init; re-zeroed by last norm block
__device__ float g_sumsq[KEYS];
__device__ unsigned g_norm_done; // static zero-init; reset by last norm block

__device__ __forceinline__ void acc4(const float4 v, float& s, float& s2) {
    s += (v.x + v.y) + (v.z + v.w);
    s2 = fmaf(v.x, v.x, s2); s2 = fmaf(v.y, v.y, s2);
    s2 = fmaf(v.z, v.z, s2); s2 = fmaf(v.w, v.w, s2);
}

// Reduce: one warp owns a contiguous range of global points [g0, g1).
// Segment runs derived from the 33-entry offs array (batch_indices is
// non-decreasing) -> pure 12x LDG.128 + FMA stream.
__global__ __launch_bounds__(RTPB, 1) void pln_reduce_kernel(
    const float4* __restrict__ x4, const int* __restrict__ offs)
{
    const int P = Bc * Nc;
    int wid    = (blockIdx.x * blockDim.x + threadIdx.x) >> 5;
    int lane   = threadIdx.x & 31;
    int totalW = (RGRID * RTPB) >> 5;                        // 4736 warps
    int chunk  = (((P + totalW - 1) / totalW) + 15) & ~15;   // 176
    int g0 = wid * chunk;
    int g1 = min(g0 + chunk, P);

    if (g0 < g1) {
        int g = g0;
        while (g < g1) {
            int b = g / Nc;
            int n = g - b * Nc;
            int nlimit = min(Nc, n + (g1 - g));   // batch-local end of range

            // binary search: largest seg with offs[seg] <= n  (offs[0]=0)
            int seg = 0;
            #pragma unroll
            for (int step = 16; step; step >>= 1) {
                int cand = seg + step;
                if (cand <= Sc - 1 && __ldg(&offs[cand]) <= n) seg = cand;
            }

            while (n < nlimit) {
                int rend = min(nlimit, __ldg(&offs[seg + 1]));
                int key  = b * Sc + seg;

                float sA = 0.f, sB = 0.f, s2A = 0.f, s2B = 0.f;
                const float4* base = x4 + ((size_t)b * Nc + n) * C4;

                // 16-point groups: 384 consecutive float4s, 12 LDG.128/lane.
                for (; n + 16 <= rend; n += 16, base += 384) {
                    float4 v0  = __ldg(base + lane);
                    float4 v1  = __ldg(base + lane + 32);
                    float4 v2  = __ldg(base + lane + 64);
                    float4 v3  = __ldg(base + lane + 96);
                    float4 v4  = __ldg(base + lane + 128);
                    float4 v5  = __ldg(base + lane + 160);
                    float4 v6  = __ldg(base + lane + 192);
                    float4 v7  = __ldg(base + lane + 224);
                    float4 v8  = __ldg(base + lane + 256);
                    float4 v9  = __ldg(base + lane + 288);
                    float4 v10 = __ldg(base + lane + 320);
                    float4 v11 = __ldg(base + lane + 352);
                    acc4(v0,  sA, s2A); acc4(v1,  sB, s2B);
                    acc4(v2,  sA, s2A); acc4(v3,  sB, s2B);
                    acc4(v4,  sA, s2A); acc4(v5,  sB, s2B);
                    acc4(v6,  sA, s2A); acc4(v7,  sB, s2B);
                    acc4(v8,  sA, s2A); acc4(v9,  sB, s2B);
                    acc4(v10, sA, s2A); acc4(v11, sB, s2B);
                }
                // 8-point group (at most one)
                for (; n + 8 <= rend; n += 8, base += 192) {
                    float4 v0 = __ldg(base + lane);
                    float4 v1 = __ldg(base + lane + 32);
                    float4 v2 = __ldg(base + lane + 64);
                    float4 v3 = __ldg(base + lane + 96);
                    float4 v4 = __ldg(base + lane + 128);
                    float4 v5 = __ldg(base + lane + 160);
                    acc4(v0, sA, s2A); acc4(v1, sB, s2B);
                    acc4(v2, sA, s2A); acc4(v3, sB, s2B);
                    acc4(v4, sA, s2A); acc4(v5, sB, s2B);
                }
                // remainder: single points, 24 active lanes
                for (; n < rend; ++n, base += 24) {
                    if (lane < C4) {
                        float4 v = __ldg(base + lane);
                        acc4(v, sA, s2A);
                    }
                }

                // flush this run
                float s = sA + sB, s2 = s2A + s2B;
                #pragma unroll
                for (int o = 16; o; o >>= 1) {
                    s  += __shfl_xor_sync(0xffffffffu, s,  o);
                    s2 += __shfl_xor_sync(0xffffffffu, s2, o);
                }
                if (lane == 0) {
                    atomicAdd(&g_sum[key],   s);
                    atomicAdd(&g_sumsq[key], s2);
                }
                if (n < nlimit) ++seg;   // next segment in this batch
            }
            g = b * Nc + nlimit;         // next batch-slice re-searches seg
        }
    }

#if __CUDA_ARCH__ >= 900
    // Allow the dependent norm kernel to start its prologue early; its
    // cudaGridDependencySynchronize() still waits for our memory to land.
    cudaTriggerProgrammaticLaunchCompletion();
#endif
}

// Norm: finalize folded into the prologue. Each block computes the 128
// (mean, inv_std) pairs into smem, then streams with sc/sh derived in-loop.
// Stats zeroing: the last block to pass the prologue zeroes g_sum/g_sumsq
// and resets the counter (every block reads stats BEFORE incrementing).
__global__ __launch_bounds__(NTPB) void pln_norm_kernel(
    const float4* __restrict__ x4, const int* __restrict__ idx,
    const int* __restrict__ offs,
    const float4* __restrict__ w4, const float4* __restrict__ b4,
    float4* __restrict__ out4)
{
#if __CUDA_ARCH__ >= 900
    cudaGridDependencySynchronize();   // reduce's atomics are now visible
#endif
    __shared__ float2 s_mi[KEYS];      // [key] -> (mean, inv_std)

    if (threadIdx.x < KEYS) {
        int k   = threadIdx.x;
        int seg = k & (Sc - 1);
        float cnt = (float)(__ldg(&offs[seg + 1]) - __ldg(&offs[seg])) * (float)Cc;
        float m   = __ldcg(&g_sum[k])   / cnt;
        float var = __ldcg(&g_sumsq[k]) / cnt - m * m;
        s_mi[k] = make_float2(m, rsqrtf(var + EPSF));
    }
    __syncthreads();                   // all reads of stats done for this block
    if (threadIdx.x == 0) {
        if (atomicAdd(&g_norm_done, 1u) == NGRID - 1) {
            for (int k = 0; k < KEYS; ++k) { g_sum[k] = 0.f; g_sumsq[k] = 0.f; }
            __threadfence();
            g_norm_done = 0;           // replay-clean
        }
    }

    const int P = Bc * Nc;
    const int E = P * C4;              // 19,200,000 float4s
    int T   = NGRID * NTPB;            // 303360, multiple of 24
    int tid = blockIdx.x * blockDim.x + threadIdx.x;
    int dp  = T / C4;

    int p  = tid / C4;
    int c4 = tid - p * C4;
    int b  = p / Nc;
    int n  = p - b * Nc;

    float4 wv = __ldg(w4 + c4);        // loop-invariant per thread
    float4 bv = __ldg(b4 + c4);

    for (int e = tid; e < E; e += T) {
        int key = (b * Sc + __ldg(&idx[n])) & (KEYS - 1);
        float2 mi = s_mi[key];         // broadcast LDS (24 threads share key)
        float4 xv = __ldcs(x4 + e);
        float4 o; float t, sh;
        t = mi.y * wv.x; sh = fmaf(-mi.x, t, bv.x); o.x = fmaf(xv.x, t, sh);
        t = mi.y * wv.y; sh = fmaf(-mi.x, t, bv.y); o.y = fmaf(xv.y, t, sh);
        t = mi.y * wv.z; sh = fmaf(-mi.x, t, bv.z); o.z = fmaf(xv.z, t, sh);
        t = mi.y * wv.w; sh = fmaf(-mi.x, t, bv.w); o.w = fmaf(xv.w, t, sh);
        __stcs(out4 + e, o);
        n += dp;
        if (n >= Nc) { n -= Nc; ++b; }
    }
}

extern "C" void kernel_launch(void* const* d_in, const int* in_sizes, int n_in,
                              void* d_out, int out_size) {
    const float4* x4   = (const float4*)d_in[0];
    const int*    offs = (const int*)d_in[1];
    const int*    idx  = (const int*)d_in[2];
    const float4* w4   = (const float4*)d_in[3];
    const float4* b4   = (const float4*)d_in[4];
    float4* out4 = (float4*)d_out;

    pln_reduce_kernel<<<RGRID, RTPB>>>(x4, offs);

    // Norm with programmatic dependent launch: ramp overlaps the reduce tail;
    // cudaGridDependencySynchronize() in the kernel enforces correctness.
    cudaLaunchConfig_t cfg = {};
    cfg.gridDim  = dim3(NGRID, 1, 1);
    cfg.blockDim = dim3(NTPB, 1, 1);
    cfg.dynamicSmemBytes = 0;
    cfg.stream = 0;
    cudaLaunchAttribute attrs[1];
    attrs[0].id = cudaLaunchAttributeProgrammaticStreamSerialization;
    attrs[0].val.programmaticStreamSerializationAllowed = 1;
    cfg.attrs = attrs;
    cfg.numAttrs = 1;
    cudaLaunchKernelEx(&cfg, pln_norm_kernel, x4, idx, offs, w4, b4, out4);
}